// round 1
// baseline (speedup 1.0000x reference)
#include <cuda_runtime.h>
#include <math.h>

#define BATCH 4
#define NTOK 257
#define CIN 1152
#define DFE 512
#define DH 128
#define IMG 224
#define N0 512
#define F0 4
#define N1 2048
#define F1 8
#define KSTG 515           // 3 + DFE
#define XLD 520            // padded row for g_x
#define HLD 2048           // row stride of g_h

// ------------------------- scratch (no allocations allowed) -------------------------
__device__ float g_feat1[(size_t)BATCH * 2 * DFE * NTOK];   // 4x1024x257
__device__ float g_feat2[(size_t)BATCH * DFE * NTOK];       // 4x512x257
__device__ float g_lf[(size_t)BATCH * 256 * DFE];           // [b][cell][c]
__device__ float g_w2c[BATCH * 12];                         // top-3 rows of inv(c2w*flip)
__device__ int   g_pinfo[BATCH * N1];                       // visible? iy*224+ix : -1
__device__ float g_x[(size_t)BATCH * N1 * XLD];             // [b][n][k] (k=0..2 pcd, 3..514 cond)
__device__ float g_h[(size_t)BATCH * DH * HLD];             // [b][m][n]

// ------------------------- generic NN GEMM: C = act(A@B + bias) -------------------------
// A: MxK row-major (shared over batch). B: KxN row-major, batched. C: MxN row-major, batched.
__global__ __launch_bounds__(256) void gemm_nn(
    const float* __restrict__ A, const float* __restrict__ Bm,
    const float* __restrict__ bias, float* __restrict__ C,
    int M, int N, int K, size_t strideB, size_t strideC, int relu)
{
    __shared__ __align__(16) float As[16][68];
    __shared__ __align__(16) float Bs[16][68];
    const int bx = blockIdx.x, by = blockIdx.y, bz = blockIdx.z;
    const float* Bp = Bm + (size_t)bz * strideB;
    float* Cp = C + (size_t)bz * strideC;
    const int tid = threadIdx.x;
    const int tx = tid & 15, ty = tid >> 4;
    const int m0 = by * 64, n0 = bx * 64;

    float acc[4][4];
#pragma unroll
    for (int i = 0; i < 4; i++)
#pragma unroll
        for (int j = 0; j < 4; j++) acc[i][j] = 0.f;

    for (int k0 = 0; k0 < K; k0 += 16) {
        // A tile 64(m) x 16(k): coalesced along k
#pragma unroll
        for (int i = 0; i < 4; i++) {
            int idx = tid + i * 256;
            int m = idx >> 4, k = idx & 15;
            float v = 0.f;
            if (m0 + m < M && k0 + k < K) v = A[(size_t)(m0 + m) * K + (k0 + k)];
            As[k][m] = v;
        }
        // B tile 16(k) x 64(n): coalesced along n
#pragma unroll
        for (int i = 0; i < 4; i++) {
            int idx = tid + i * 256;
            int k = idx >> 6, n = idx & 63;
            float v = 0.f;
            if (k0 + k < K && n0 + n < N) v = Bp[(size_t)(k0 + k) * N + (n0 + n)];
            Bs[k][n] = v;
        }
        __syncthreads();
#pragma unroll
        for (int kk = 0; kk < 16; kk++) {
            float4 a4 = *(const float4*)&As[kk][ty * 4];
            float4 b4 = *(const float4*)&Bs[kk][tx * 4];
            float a[4] = {a4.x, a4.y, a4.z, a4.w};
            float b[4] = {b4.x, b4.y, b4.z, b4.w};
#pragma unroll
            for (int i = 0; i < 4; i++)
#pragma unroll
                for (int j = 0; j < 4; j++) acc[i][j] += a[i] * b[j];
        }
        __syncthreads();
    }
#pragma unroll
    for (int i = 0; i < 4; i++) {
        int m = m0 + ty * 4 + i;
        if (m >= M) continue;
        float bv = bias[m];
#pragma unroll
        for (int j = 0; j < 4; j++) {
            int n = n0 + tx * 4 + j;
            if (n >= N) continue;
            float v = acc[i][j] + bv;
            if (relu) v = fmaxf(v, 0.f);
            Cp[(size_t)m * N + n] = v;
        }
    }
}

// ------------------------- feat2 -> g_lf transpose (drop token 0) -------------------------
__global__ void make_lf()
{
    int i = blockIdx.x * 256 + threadIdx.x;       // over b*256*512, c fastest
    int c = i & (DFE - 1);
    int t = (i >> 9) & 255;
    int b = i >> 17;
    g_lf[i] = g_feat2[((size_t)b * DFE + c) * NTOK + (t + 1)];
}

// ------------------------- camera setup: inv(c2w * flip), top 3 rows -------------------------
__global__ void setup_w2c_kernel(const float* __restrict__ c2w)
{
    int b = threadIdx.x;
    if (b >= BATCH) return;
    float m[4][4], inv[4][4];
    for (int r = 0; r < 4; r++)
        for (int c = 0; c < 4; c++) {
            float v = c2w[b * 16 + r * 4 + c];
            if (r < 3 && (c == 1 || c == 2)) v = -v;
            m[r][c] = v;
            inv[r][c] = (r == c) ? 1.f : 0.f;
        }
    for (int col = 0; col < 4; col++) {
        int piv = col;
        float best = fabsf(m[col][col]);
        for (int r = col + 1; r < 4; r++) {
            float a = fabsf(m[r][col]);
            if (a > best) { best = a; piv = r; }
        }
        if (piv != col)
            for (int c = 0; c < 4; c++) {
                float t = m[col][c]; m[col][c] = m[piv][c]; m[piv][c] = t;
                t = inv[col][c]; inv[col][c] = inv[piv][c]; inv[piv][c] = t;
            }
        float d = 1.f / m[col][col];
        for (int c = 0; c < 4; c++) { m[col][c] *= d; inv[col][c] *= d; }
        for (int r = 0; r < 4; r++)
            if (r != col) {
                float f = m[r][col];
                for (int c = 0; c < 4; c++) { m[r][c] -= f * m[col][c]; inv[r][c] -= f * inv[col][c]; }
            }
    }
    for (int i = 0; i < 12; i++) g_w2c[b * 12 + i] = inv[i / 4][i % 4];
}

// ------------------------- projection + z-buffer visibility (one block per batch) -------------------------
__global__ __launch_bounds__(1024) void project_vis(
    const float* __restrict__ pts, const float* __restrict__ Kin, int Npts)
{
    __shared__ float sz[N1];
    __shared__ int spix[N1];
    const int b = blockIdx.x;
    const float* w = g_w2c + b * 12;
    const float fx = Kin[b * 9 + 0], cx = Kin[b * 9 + 2];
    const float fy = Kin[b * 9 + 4], cy = Kin[b * 9 + 5];

    for (int i = threadIdx.x; i < Npts; i += blockDim.x) {
        const float* p = pts + (size_t)(b * Npts + i) * 3;
        float x = p[0], y = p[1], z = p[2];
        float camx = w[0] * x + w[1] * y + w[2] * z + w[3];
        float camy = w[4] * x + w[5] * y + w[6] * z + w[7];
        float camz = w[8] * x + w[9] * y + w[10] * z + w[11];
        float zs = (fabsf(camz) > 1e-8f) ? camz : 1e-8f;
        float px = fx * camx / zs + cx;
        float py = fy * camy / zs + cy;
        int ix = (int)floorf(px);
        int iy = (int)floorf(py);
        bool valid = (camz > 1e-6f) && ix >= 0 && ix < IMG && iy >= 0 && iy < IMG;
        spix[i] = valid ? (iy * IMG + ix) : -1;
        sz[i] = camz;
    }
    __syncthreads();
    for (int i = threadIdx.x; i < Npts; i += blockDim.x) {
        int mypix = spix[i];
        float myz = sz[i];
        bool vis = (mypix >= 0);
        if (vis) {
            for (int j = 0; j < Npts; j++) {
                if (spix[j] == mypix) {
                    float zj = sz[j];
                    if (zj < myz || (zj == myz && j < i)) { vis = false; break; }
                }
            }
        }
        g_pinfo[b * N1 + i] = vis ? mypix : -1;
    }
}

// ------------------------- gather: build X = [pcd(3); up_cond(512)] point-major -------------------------
__global__ __launch_bounds__(128) void gather_cond(const float* __restrict__ pts, int Npts)
{
    const int pblk = blockIdx.x;              // b*Npts + n
    const int b = pblk / Npts;
    const int n = pblk % Npts;
    const int tid = threadIdx.x;
    float* xo = g_x + ((size_t)b * N1 + n) * XLD;
    if (tid < 3) xo[tid] = pts[(size_t)pblk * 3 + tid];
    int pinfo = g_pinfo[b * N1 + n];
    if (pinfo < 0) {
        for (int c = tid; c < DFE; c += 128) xo[3 + c] = 0.f;
        return;
    }
    int iy = pinfo / IMG, ix = pinfo - iy * IMG;
    // jax half-pixel bilinear from 16x16 grid; clamped taps == normalized triangle weights here
    float sfx = (ix + 0.5f) * (16.f / 224.f) - 0.5f;
    float sfy = (iy + 0.5f) * (16.f / 224.f) - 0.5f;
    int jx0 = (int)floorf(sfx); float fxw = sfx - (float)jx0;
    int jy0 = (int)floorf(sfy); float fyw = sfy - (float)jy0;
    int x0 = min(max(jx0, 0), 15), x1 = min(max(jx0 + 1, 0), 15);
    int y0 = min(max(jy0, 0), 15), y1 = min(max(jy0 + 1, 0), 15);
    float w00 = (1.f - fyw) * (1.f - fxw);
    float w01 = (1.f - fyw) * fxw;
    float w10 = fyw * (1.f - fxw);
    float w11 = fyw * fxw;
    const float* l00 = g_lf + ((size_t)b * 256 + y0 * 16 + x0) * DFE;
    const float* l01 = g_lf + ((size_t)b * 256 + y0 * 16 + x1) * DFE;
    const float* l10 = g_lf + ((size_t)b * 256 + y1 * 16 + x0) * DFE;
    const float* l11 = g_lf + ((size_t)b * 256 + y1 * 16 + x1) * DFE;
    for (int c = tid; c < DFE; c += 128)
        xo[3 + c] = w00 * l00[c] + w01 * l01[c] + w10 * l10[c] + w11 * l11[c];
}

// ------------------------- stage GEMM1: g_h = relu(W1(128x515) @ g_x^T + b) -------------------------
__global__ __launch_bounds__(256) void stage_gemm(
    const float* __restrict__ A, const float* __restrict__ bias, int N)
{
    __shared__ __align__(16) float As[16][68];
    __shared__ __align__(16) float Bs[16][68];
    const int bx = blockIdx.x, by = blockIdx.y, bz = blockIdx.z;
    const int tid = threadIdx.x;
    const int tx = tid & 15, ty = tid >> 4;
    const int m0 = by * 64, n0 = bx * 64;
    const float* Bp = g_x + (size_t)bz * N1 * XLD;
    float* Cp = g_h + (size_t)bz * DH * HLD;

    float acc[4][4];
#pragma unroll
    for (int i = 0; i < 4; i++)
#pragma unroll
        for (int j = 0; j < 4; j++) acc[i][j] = 0.f;

    for (int k0 = 0; k0 < KSTG; k0 += 16) {
#pragma unroll
        for (int i = 0; i < 4; i++) {
            int idx = tid + i * 256;
            int m = idx >> 4, k = idx & 15;
            float v = 0.f;
            if (k0 + k < KSTG) v = A[(size_t)(m0 + m) * KSTG + (k0 + k)];   // M==128 exact
            As[k][m] = v;
        }
#pragma unroll
        for (int i = 0; i < 4; i++) {
            int idx = tid + i * 256;
            int n = idx >> 4, k = idx & 15;
            float v = 0.f;
            if (n0 + n < N && k0 + k < KSTG) v = Bp[(size_t)(n0 + n) * XLD + (k0 + k)];
            Bs[k][n] = v;
        }
        __syncthreads();
#pragma unroll
        for (int kk = 0; kk < 16; kk++) {
            float4 a4 = *(const float4*)&As[kk][ty * 4];
            float4 b4 = *(const float4*)&Bs[kk][tx * 4];
            float a[4] = {a4.x, a4.y, a4.z, a4.w};
            float b[4] = {b4.x, b4.y, b4.z, b4.w};
#pragma unroll
            for (int i = 0; i < 4; i++)
#pragma unroll
                for (int j = 0; j < 4; j++) acc[i][j] += a[i] * b[j];
        }
        __syncthreads();
    }
#pragma unroll
    for (int i = 0; i < 4; i++) {
        int m = m0 + ty * 4 + i;
        float bv = bias[m];
#pragma unroll
        for (int j = 0; j < 4; j++) {
            int n = n0 + tx * 4 + j;
            if (n < N) Cp[(size_t)m * HLD + n] = fmaxf(acc[i][j] + bv, 0.f);
        }
    }
}

// ------------------------- stage GEMM2 + tanh + repeat/offset scatter -------------------------
template <int F>
__global__ __launch_bounds__(128) void stage_out(
    const float* __restrict__ ow, const float* __restrict__ ob,
    const float* __restrict__ pts_in, float* __restrict__ pts_out, int Npts)
{
    __shared__ float s_ow[F * 3][DH];
    __shared__ float s_ob[F * 3];
    const int b = blockIdx.y;
    const int tid = threadIdx.x;
    for (int i = tid; i < F * 3 * DH; i += 128) s_ow[i / DH][i % DH] = ow[i];
    if (tid < F * 3) s_ob[tid] = ob[tid];
    __syncthreads();
    const int n = blockIdx.x * 128 + tid;
    if (n >= Npts) return;
    const float* hp = g_h + (size_t)b * DH * HLD;
    float acc[F * 3];
#pragma unroll
    for (int r = 0; r < F * 3; r++) acc[r] = s_ob[r];
    for (int o = 0; o < DH; o++) {
        float hv = hp[(size_t)o * HLD + n];
#pragma unroll
        for (int r = 0; r < F * 3; r++) acc[r] += s_ow[r][o] * hv;
    }
    float p[3];
    p[0] = pts_in[(size_t)(b * Npts + n) * 3 + 0];
    p[1] = pts_in[(size_t)(b * Npts + n) * 3 + 1];
    p[2] = pts_in[(size_t)(b * Npts + n) * 3 + 2];
#pragma unroll
    for (int k = 0; k < F; k++) {
#pragma unroll
        for (int c = 0; c < 3; c++) {
            size_t oidx = ((size_t)b * Npts * F + (size_t)n * F + k) * 3 + c;
            pts_out[oidx] = p[c] + tanhf(acc[k * 3 + c]);
        }
    }
}

// ------------------------- launch -------------------------
extern "C" void kernel_launch(void* const* d_in, const int* in_sizes, int n_in,
                              void* d_out, int out_size)
{
    const float* points = (const float*)d_in[0];
    const float* tokens = (const float*)d_in[1];
    const float* c2w    = (const float*)d_in[2];
    const float* Kin    = (const float*)d_in[3];
    const float* w1     = (const float*)d_in[4];
    const float* b1     = (const float*)d_in[5];
    const float* w2     = (const float*)d_in[6];
    const float* b2     = (const float*)d_in[7];
    const float* s0w1   = (const float*)d_in[8];
    const float* s0b1   = (const float*)d_in[9];
    const float* s0ow   = (const float*)d_in[10];
    const float* s0ob   = (const float*)d_in[11];
    const float* s1w1   = (const float*)d_in[12];
    const float* s1b1   = (const float*)d_in[13];
    const float* s1ow   = (const float*)d_in[14];
    const float* s1ob   = (const float*)d_in[15];

    float* out0 = (float*)d_out;                       // (4, 2048, 3)
    float* out1 = out0 + (size_t)BATCH * N0 * F0 * 3;  // (4, 16384, 3)

    float *feat1, *feat2;
    cudaGetSymbolAddress((void**)&feat1, g_feat1);
    cudaGetSymbolAddress((void**)&feat2, g_feat2);

    // token MLP
    gemm_nn<<<dim3(5, 16, BATCH), 256>>>(w1, tokens, b1, feat1,
        1024, NTOK, CIN, (size_t)CIN * NTOK, (size_t)1024 * NTOK, 1);
    gemm_nn<<<dim3(5, 8, BATCH), 256>>>(w2, feat1, b2, feat2,
        512, NTOK, 1024, (size_t)1024 * NTOK, (size_t)512 * NTOK, 0);
    make_lf<<<BATCH * 256 * DFE / 256, 256>>>();
    setup_w2c_kernel<<<1, BATCH>>>(c2w);

    // stage 0
    project_vis<<<BATCH, 1024>>>(points, Kin, N0);
    gather_cond<<<BATCH * N0, 128>>>(points, N0);
    stage_gemm<<<dim3(N0 / 64, 2, BATCH), 256>>>(s0w1, s0b1, N0);
    stage_out<F0><<<dim3(N0 / 128, BATCH), 128>>>(s0ow, s0ob, points, out0, N0);

    // stage 1 (input = stage-0 output, already in d_out)
    project_vis<<<BATCH, 1024>>>(out0, Kin, N1);
    gather_cond<<<BATCH * N1, 128>>>(out0, N1);
    stage_gemm<<<dim3(N1 / 64, 2, BATCH), 256>>>(s1w1, s1b1, N1);
    stage_out<F1><<<dim3(N1 / 128, BATCH), 128>>>(s1ow, s1ob, out0, out1, N1);
}

// round 2
// speedup vs baseline: 1.4982x; 1.4982x over previous
#include <cuda_runtime.h>
#include <math.h>

#define BATCH 4
#define CIN 1152
#define IMG 224
#define NPIX (IMG*IMG)
#define N0 512
#define F0 4
#define N1 2048
#define F1 8
#define KSTG 520          // padded 3+512
#define XLD 520
#define HLD 2048
#define DH 128

typedef unsigned long long ull;

// ------------------------- scratch -------------------------
__device__ float g_feat1[(size_t)BATCH*1024*256];
__device__ float g_feat2[(size_t)BATCH*512*256];
__device__ float g_lf[(size_t)BATCH*256*512];     // [b][cell][c]
__device__ float g_w2c[BATCH*12];
__device__ float g_w1p[2*DH*KSTG];                // padded/reordered stage weights
__device__ int   g_pixb[BATCH*N1];
__device__ float g_pzb[BATCH*N1];
__device__ ull   g_zbuf[BATCH*NPIX];
__device__ float g_x[(size_t)BATCH*N1*XLD];       // [b][n][k]: cond 0..511, pcd 512..514, pad 515..519 (stays 0)
__device__ float g_h[(size_t)BATCH*DH*HLD];

// ------------------------- f32x2 helpers -------------------------
__device__ __forceinline__ void ffma2(ull &d, ull a, ull b){
    asm("fma.rn.f32x2 %0, %1, %2, %0;" : "+l"(d) : "l"(a), "l"(b));
}
__device__ __forceinline__ float2 unpack2(ull v){
    float2 r; asm("mov.b64 {%0,%1}, %2;" : "=f"(r.x), "=f"(r.y) : "l"(v)); return r;
}

// ------------------------- packed-fp32 GEMM -------------------------
// C[b] = act(A @ B[b] + bias). A: 128*gridY x K row-major. C row-major (ldc).
// BLOAD: 0 = scalar row-major B (odd ldb), 1 = vec2 row-major B, 2 = B given transposed (N x K row-major).
// Microtile: 8 M-rows (as 4 f32x2 pairs) x TN cols per thread. B duplicated in smem -> no packing MOVs.
template<int BN, int TN, int BLOAD>
__global__ __launch_bounds__(128) void gemm_k(
    const float* __restrict__ A, const float* __restrict__ B,
    const float* __restrict__ bias, float* __restrict__ C,
    int K, int lda, int ldb, int ldc,
    size_t sB, size_t sC, int relu)
{
    constexpr int BNP2 = 2*BN + 8;
    __shared__ __align__(16) float As[2][8][128];
    __shared__ __align__(16) float Bs[2][8][BNP2];
    const int tid = threadIdx.x;
    const int m0 = blockIdx.y * 128;
    const int n0 = blockIdx.x * BN;
    const float* Bp = B + (size_t)blockIdx.z * sB;
    float* Cp = C + (size_t)blockIdx.z * sC;
    const int tm = tid & 15, tn = tid >> 4;

    ull acc[4][TN];
#pragma unroll
    for (int i = 0; i < 4; i++)
#pragma unroll
        for (int j = 0; j < TN; j++) acc[i][j] = 0ULL;

    constexpr int RB = (BLOAD == 0) ? (BN*8/128) : (BN*4/128);
    float4 ar0, ar1;
    float  brs[(BLOAD == 0) ? RB : 1];
    float2 brv[(BLOAD != 0) ? RB : 1];
    const float* Ap = A + (size_t)(m0 + tid) * lda;

    auto ldTile = [&](int k0){
        ar0 = *(const float4*)(Ap + k0);
        ar1 = *(const float4*)(Ap + k0 + 4);
        if (BLOAD == 0){
#pragma unroll
            for (int r = 0; r < RB; r++){
                int e = tid + r*128;
                int k = e >> 6, n = e & 63;
                brs[r] = Bp[(size_t)(k0 + k)*ldb + n0 + n];
            }
        } else if (BLOAD == 1){
#pragma unroll
            for (int r = 0; r < RB; r++){
                int e = tid + r*128;
                int k = e / (BN/2);
                int n = (e % (BN/2)) * 2;
                brv[r] = *(const float2*)&Bp[(size_t)(k0 + k)*ldb + n0 + n];
            }
        } else {
#pragma unroll
            for (int r = 0; r < RB; r++){
                int e = tid + r*128;
                int n = e >> 2, k = (e & 3)*2;
                brv[r] = *(const float2*)&Bp[(size_t)(n0 + n)*ldb + k0 + k];
            }
        }
    };
    auto stTile = [&](int buf){
        As[buf][0][tid]=ar0.x; As[buf][1][tid]=ar0.y;
        As[buf][2][tid]=ar0.z; As[buf][3][tid]=ar0.w;
        As[buf][4][tid]=ar1.x; As[buf][5][tid]=ar1.y;
        As[buf][6][tid]=ar1.z; As[buf][7][tid]=ar1.w;
        if (BLOAD == 0){
#pragma unroll
            for (int r = 0; r < RB; r++){
                int e = tid + r*128;
                int k = e >> 6, n = e & 63;
                *(float2*)&Bs[buf][k][2*n] = make_float2(brs[r], brs[r]);
            }
        } else if (BLOAD == 1){
#pragma unroll
            for (int r = 0; r < RB; r++){
                int e = tid + r*128;
                int k = e / (BN/2);
                int n = (e % (BN/2)) * 2;
                *(float4*)&Bs[buf][k][2*n] = make_float4(brv[r].x, brv[r].x, brv[r].y, brv[r].y);
            }
        } else {
#pragma unroll
            for (int r = 0; r < RB; r++){
                int e = tid + r*128;
                int n = e >> 2, k = (e & 3)*2;
                *(float2*)&Bs[buf][k  ][2*n] = make_float2(brv[r].x, brv[r].x);
                *(float2*)&Bs[buf][k+1][2*n] = make_float2(brv[r].y, brv[r].y);
            }
        }
    };

    ldTile(0); stTile(0);
    __syncthreads();
    const int T = K / 8;
    for (int t = 0; t < T; ++t){
        int cur = t & 1;
        if (t + 1 < T) ldTile((t + 1) * 8);
#pragma unroll
        for (int kk = 0; kk < 8; ++kk){
            const float* arow = &As[cur][kk][tm*8];
            longlong2 a01 = *(const longlong2*)(arow);
            longlong2 a23 = *(const longlong2*)(arow + 4);
            ull av[4] = {(ull)a01.x, (ull)a01.y, (ull)a23.x, (ull)a23.y};
            ull bv[TN];
#pragma unroll
            for (int jq = 0; jq < TN/2; jq++){
                longlong2 bq = *(const longlong2*)&Bs[cur][kk][(tn*TN + 2*jq)*2];
                bv[2*jq] = (ull)bq.x; bv[2*jq+1] = (ull)bq.y;
            }
#pragma unroll
            for (int i = 0; i < 4; i++)
#pragma unroll
                for (int j = 0; j < TN; j++) ffma2(acc[i][j], av[i], bv[j]);
        }
        if (t + 1 < T) stTile(cur ^ 1);
        __syncthreads();
    }

#pragma unroll
    for (int i = 0; i < 4; i++){
        int m = m0 + tm*8 + 2*i;
        float b0 = bias[m], b1 = bias[m+1];
#pragma unroll
        for (int j = 0; j < TN; j++){
            float2 v = unpack2(acc[i][j]);
            v.x += b0; v.y += b1;
            if (relu){ v.x = fmaxf(v.x, 0.f); v.y = fmaxf(v.y, 0.f); }
            int n = n0 + tn*TN + j;
            Cp[(size_t)m*ldc + n]     = v.x;
            Cp[(size_t)(m+1)*ldc + n] = v.y;
        }
    }
}

// ------------------------- feat2 -> g_lf tiled transpose -------------------------
__global__ void transpose_lf(){
    __shared__ float s[32][33];
    int b = blockIdx.z;
    int t0 = blockIdx.x * 32;
    int c0 = blockIdx.y * 32;
    int x = threadIdx.x, y = threadIdx.y;   // 32 x 8
#pragma unroll
    for (int r = 0; r < 32; r += 8)
        s[y + r][x] = g_feat2[((size_t)b*512 + c0 + y + r)*256 + t0 + x];
    __syncthreads();
#pragma unroll
    for (int r = 0; r < 32; r += 8)
        g_lf[((size_t)b*256 + t0 + y + r)*512 + c0 + x] = s[x][y + r];
}

// ------------------------- pad/reorder stage weights -------------------------
__global__ void pad_w(const float* __restrict__ w0, const float* __restrict__ w1){
    int i = blockIdx.x*256 + threadIdx.x;
    if (i >= 2*DH*KSTG) return;
    int s = i / (DH*KSTG);
    int r = i - s*(DH*KSTG);
    int m = r / KSTG, k = r - m*KSTG;
    const float* w = s ? w1 : w0;
    float v = 0.f;
    if (k < 512) v = w[m*515 + 3 + k];          // cond channels
    else if (k < 515) v = w[m*515 + (k - 512)]; // pcd xyz
    g_w1p[i] = v;
}

// ------------------------- camera setup -------------------------
__global__ void setup_w2c_kernel(const float* __restrict__ c2w)
{
    int b = threadIdx.x;
    if (b >= BATCH) return;
    float m[4][4], inv[4][4];
    for (int r = 0; r < 4; r++)
        for (int c = 0; c < 4; c++) {
            float v = c2w[b*16 + r*4 + c];
            if (r < 3 && (c == 1 || c == 2)) v = -v;
            m[r][c] = v;
            inv[r][c] = (r == c) ? 1.f : 0.f;
        }
    for (int col = 0; col < 4; col++) {
        int piv = col; float best = fabsf(m[col][col]);
        for (int r = col+1; r < 4; r++){ float a = fabsf(m[r][col]); if (a > best){ best = a; piv = r; } }
        if (piv != col)
            for (int c = 0; c < 4; c++){
                float t = m[col][c]; m[col][c] = m[piv][c]; m[piv][c] = t;
                t = inv[col][c]; inv[col][c] = inv[piv][c]; inv[piv][c] = t;
            }
        float d = 1.f / m[col][col];
        for (int c = 0; c < 4; c++){ m[col][c] *= d; inv[col][c] *= d; }
        for (int r = 0; r < 4; r++)
            if (r != col){
                float f = m[r][col];
                for (int c = 0; c < 4; c++){ m[r][c] -= f*m[col][c]; inv[r][c] -= f*inv[col][c]; }
            }
    }
    for (int i = 0; i < 12; i++) g_w2c[b*12 + i] = inv[i/4][i%4];
}

// ------------------------- z-buffer visibility -------------------------
__global__ void reset_zbuf(){
    int i = blockIdx.x*256 + threadIdx.x;
    if (i < BATCH*NPIX) g_zbuf[i] = ~0ULL;
}

__global__ void project(const float* __restrict__ pts, const float* __restrict__ Kin, int Npts){
    int i = blockIdx.x*256 + threadIdx.x;
    if (i >= BATCH*Npts) return;
    int b = i / Npts, n = i - b*Npts;
    const float* w = g_w2c + b*12;
    float x = pts[(size_t)i*3], y = pts[(size_t)i*3+1], z = pts[(size_t)i*3+2];
    float camx = w[0]*x + w[1]*y + w[2]*z + w[3];
    float camy = w[4]*x + w[5]*y + w[6]*z + w[7];
    float camz = w[8]*x + w[9]*y + w[10]*z + w[11];
    float zs = (fabsf(camz) > 1e-8f) ? camz : 1e-8f;
    float fx = Kin[b*9+0], cxk = Kin[b*9+2], fy = Kin[b*9+4], cyk = Kin[b*9+5];
    float px = fx*camx/zs + cxk;
    float py = fy*camy/zs + cyk;
    int ix = (int)floorf(px), iy = (int)floorf(py);
    bool valid = (camz > 1e-6f) && ix >= 0 && ix < IMG && iy >= 0 && iy < IMG;
    int pix = valid ? iy*IMG + ix : -1;
    g_pixb[b*N1 + n] = pix;
    g_pzb[b*N1 + n] = camz;
    if (valid)
        atomicMin(&g_zbuf[(size_t)b*NPIX + pix], ((ull)__float_as_uint(camz) << 32) | (unsigned)n);
}

// ------------------------- gather cond + visibility check -------------------------
__global__ __launch_bounds__(128) void gather_cond(const float* __restrict__ pts, int Npts){
    int blk = blockIdx.x;
    int b = blk / Npts, n = blk - b*Npts;
    int tid = threadIdx.x;
    float* xo = g_x + ((size_t)b*N1 + n)*XLD;
    if (tid < 3) xo[512 + tid] = pts[(size_t)blk*3 + tid];
    int pix = g_pixb[b*N1 + n];
    bool vis = false;
    if (pix >= 0){
        ull key = ((ull)__float_as_uint(g_pzb[b*N1 + n]) << 32) | (unsigned)n;
        vis = (g_zbuf[(size_t)b*NPIX + pix] == key);
    }
    if (!vis){
        *(float4*)&xo[tid*4] = make_float4(0.f, 0.f, 0.f, 0.f);
        return;
    }
    int iy = pix / IMG, ix = pix - iy*IMG;
    float sfx = (ix + 0.5f)*(16.f/224.f) - 0.5f;
    float sfy = (iy + 0.5f)*(16.f/224.f) - 0.5f;
    int jx0 = (int)floorf(sfx); float fxw = sfx - (float)jx0;
    int jy0 = (int)floorf(sfy); float fyw = sfy - (float)jy0;
    int x0 = min(max(jx0, 0), 15), x1 = min(max(jx0+1, 0), 15);
    int y0 = min(max(jy0, 0), 15), y1 = min(max(jy0+1, 0), 15);
    float w00 = (1.f-fyw)*(1.f-fxw), w01 = (1.f-fyw)*fxw;
    float w10 = fyw*(1.f-fxw),       w11 = fyw*fxw;
    const float4* l00 = (const float4*)(g_lf + ((size_t)b*256 + y0*16 + x0)*512);
    const float4* l01 = (const float4*)(g_lf + ((size_t)b*256 + y0*16 + x1)*512);
    const float4* l10 = (const float4*)(g_lf + ((size_t)b*256 + y1*16 + x0)*512);
    const float4* l11 = (const float4*)(g_lf + ((size_t)b*256 + y1*16 + x1)*512);
    float4 v00 = l00[tid], v01 = l01[tid], v10 = l10[tid], v11 = l11[tid];
    float4 o;
    o.x = w00*v00.x + w01*v01.x + w10*v10.x + w11*v11.x;
    o.y = w00*v00.y + w01*v01.y + w10*v10.y + w11*v11.y;
    o.z = w00*v00.z + w01*v01.z + w10*v10.z + w11*v11.z;
    o.w = w00*v00.w + w01*v01.w + w10*v10.w + w11*v11.w;
    *(float4*)&xo[tid*4] = o;
}

// ------------------------- output head: tanh offsets + scatter -------------------------
template <int F>
__global__ __launch_bounds__(128) void stage_out(
    const float* __restrict__ ow, const float* __restrict__ ob,
    const float* __restrict__ pts_in, float* __restrict__ pts_out, int Npts)
{
    __shared__ float s_ow[F*3][DH];
    __shared__ float s_ob[F*3];
    const int b = blockIdx.y;
    const int tid = threadIdx.x;
    for (int i = tid; i < F*3*DH; i += 128) s_ow[i / DH][i % DH] = ow[i];
    if (tid < F*3) s_ob[tid] = ob[tid];
    __syncthreads();
    const int n = blockIdx.x*128 + tid;
    if (n >= Npts) return;
    const float* hp = g_h + (size_t)b*DH*HLD;
    float acc[F*3];
#pragma unroll
    for (int r = 0; r < F*3; r++) acc[r] = s_ob[r];
    for (int o = 0; o < DH; o++){
        float hv = hp[(size_t)o*HLD + n];
#pragma unroll
        for (int r = 0; r < F*3; r++) acc[r] += s_ow[r][o] * hv;
    }
    float p[3];
    p[0] = pts_in[(size_t)(b*Npts + n)*3 + 0];
    p[1] = pts_in[(size_t)(b*Npts + n)*3 + 1];
    p[2] = pts_in[(size_t)(b*Npts + n)*3 + 2];
#pragma unroll
    for (int k = 0; k < F; k++)
#pragma unroll
        for (int c = 0; c < 3; c++){
            size_t oidx = ((size_t)b*Npts*F + (size_t)n*F + k)*3 + c;
            pts_out[oidx] = p[c] + tanhf(acc[k*3 + c]);
        }
}

// ------------------------- launch -------------------------
extern "C" void kernel_launch(void* const* d_in, const int* in_sizes, int n_in,
                              void* d_out, int out_size)
{
    const float* points = (const float*)d_in[0];
    const float* tokens = (const float*)d_in[1];
    const float* c2w    = (const float*)d_in[2];
    const float* Kin    = (const float*)d_in[3];
    const float* w1     = (const float*)d_in[4];
    const float* b1     = (const float*)d_in[5];
    const float* w2     = (const float*)d_in[6];
    const float* b2     = (const float*)d_in[7];
    const float* s0w1   = (const float*)d_in[8];
    const float* s0b1   = (const float*)d_in[9];
    const float* s0ow   = (const float*)d_in[10];
    const float* s0ob   = (const float*)d_in[11];
    const float* s1w1   = (const float*)d_in[12];
    const float* s1b1   = (const float*)d_in[13];
    const float* s1ow   = (const float*)d_in[14];
    const float* s1ob   = (const float*)d_in[15];

    float* out0 = (float*)d_out;                       // (4, 2048, 3)
    float* out1 = out0 + (size_t)BATCH*N0*F0*3;        // (4, 16384, 3)

    float *feat1, *feat2, *w1p, *xbuf, *hbuf;
    cudaGetSymbolAddress((void**)&feat1, g_feat1);
    cudaGetSymbolAddress((void**)&feat2, g_feat2);
    cudaGetSymbolAddress((void**)&w1p,   g_w1p);
    cudaGetSymbolAddress((void**)&xbuf,  g_x);
    cudaGetSymbolAddress((void**)&hbuf,  g_h);

    pad_w<<<(2*DH*KSTG + 255)/256, 256>>>(s0w1, s1w1);
    setup_w2c_kernel<<<1, BATCH>>>(c2w);
    reset_zbuf<<<(BATCH*NPIX + 255)/256, 256>>>();

    // token MLP (token 0 dropped -> N=256)
    gemm_k<64,8,0><<<dim3(4, 8, BATCH), 128>>>(w1, tokens + 1, b1, feat1,
        1152, 1152, 257, 256, (size_t)1152*257, (size_t)1024*256, 1);
    gemm_k<32,4,1><<<dim3(8, 4, BATCH), 128>>>(w2, feat1, b2, feat2,
        1024, 1024, 256, 256, (size_t)1024*256, (size_t)512*256, 0);
    transpose_lf<<<dim3(8, 16, BATCH), dim3(32, 8)>>>();

    // stage 0
    project<<<(BATCH*N0 + 255)/256, 256>>>(points, Kin, N0);
    gather_cond<<<BATCH*N0, 128>>>(points, N0);
    gemm_k<32,4,2><<<dim3(16, 1, BATCH), 128>>>(w1p, xbuf, s0b1, hbuf,
        KSTG, KSTG, XLD, HLD, (size_t)N1*XLD, (size_t)DH*HLD, 1);
    stage_out<F0><<<dim3(N0/128, BATCH), 128>>>(s0ow, s0ob, points, out0, N0);

    // stage 1
    reset_zbuf<<<(BATCH*NPIX + 255)/256, 256>>>();
    project<<<(BATCH*N1 + 255)/256, 256>>>(out0, Kin, N1);
    gather_cond<<<BATCH*N1, 128>>>(out0, N1);
    gemm_k<64,8,2><<<dim3(32, 1, BATCH), 128>>>(w1p + DH*KSTG, xbuf, s1b1, hbuf,
        KSTG, KSTG, XLD, HLD, (size_t)N1*XLD, (size_t)DH*HLD, 1);
    stage_out<F1><<<dim3(N1/128, BATCH), 128>>>(s1ow, s1ob, out0, out1, N1);
}

// round 3
// speedup vs baseline: 1.7624x; 1.1763x over previous
#include <cuda_runtime.h>
#include <math.h>

#define BATCH 4
#define IMG 224
#define NPIX (IMG*IMG)
#define N0 512
#define F0 4
#define N1 2048
#define F1 8
#define KPAD 544          // padded 3+512 -> 544 (=4*136, 136=17*8)
#define XLD 544
#define HLD 2048
#define DH 128
#define SPL 4             // split-K factor

typedef unsigned long long ull;

// ------------------------- scratch -------------------------
__device__ float g_part[(size_t)BATCH*SPL*1024*256];   // 16MB split-K partials (max config)
__device__ float g_feat1[(size_t)BATCH*1024*256];
__device__ float g_feat2[(size_t)BATCH*512*256];
__device__ float g_lf[(size_t)BATCH*256*512];          // [b][cell][c]
__device__ float g_w2c[BATCH*12];
__device__ float g_w1p[2*DH*KPAD];                     // padded/reordered stage weights
__device__ int   g_pixb[BATCH*N1];
__device__ float g_pzb[BATCH*N1];
__device__ ull   g_zbuf[BATCH*NPIX];
__device__ float g_x[(size_t)BATCH*N1*XLD];            // [b][n][k]: cond 0..511, pcd 512..514, pad zero
__device__ float g_h[(size_t)BATCH*DH*HLD];

// ------------------------- f32x2 helpers -------------------------
__device__ __forceinline__ void ffma2(ull &d, ull a, ull b){
    asm("fma.rn.f32x2 %0, %1, %2, %0;" : "+l"(d) : "l"(a), "l"(b));
}
__device__ __forceinline__ float2 unpack2(ull v){
    float2 r; asm("mov.b64 {%0,%1}, %2;" : "=f"(r.x), "=f"(r.y) : "l"(v)); return r;
}

// ------------------------- packed-fp32 split-K GEMM -------------------------
template<int BN, int TN, int BLOAD, int S>
__global__ __launch_bounds__(128) void gemm_k(
    const float* __restrict__ A, const float* __restrict__ B,
    float* __restrict__ Cpart, int Kc, int lda, int ldb, int N, size_t sB)
{
    constexpr int BNP2 = 2*BN + 8;
    __shared__ __align__(16) float As[2][8][128];
    __shared__ __align__(16) float Bs[2][8][BNP2];
    const int tid = threadIdx.x;
    const int m0 = blockIdx.y * 128;
    const int n0 = blockIdx.x * BN;
    const int M  = gridDim.y * 128;
    const int bz = blockIdx.z;
    const int b  = bz / S, s = bz % S;
    const float* Bp = B + (size_t)b * sB + (BLOAD == 2 ? (size_t)s*Kc : (size_t)s*Kc*ldb);
    float* Cp = Cpart + (size_t)bz * M * N;
    const int tm = tid & 15, tn = tid >> 4;

    ull acc[4][TN];
#pragma unroll
    for (int i = 0; i < 4; i++)
#pragma unroll
        for (int j = 0; j < TN; j++) acc[i][j] = 0ULL;

    constexpr int RB = (BLOAD == 0) ? (BN*8/128) : (BN*4/128);
    float4 ar0, ar1;
    float  brs[(BLOAD == 0) ? RB : 1];
    float2 brv[(BLOAD != 0) ? RB : 1];
    const float* Ap = A + (size_t)(m0 + tid) * lda + (size_t)s * Kc;

    auto ldTile = [&](int k0){
        ar0 = *(const float4*)(Ap + k0);
        ar1 = *(const float4*)(Ap + k0 + 4);
        if (BLOAD == 0){
#pragma unroll
            for (int r = 0; r < RB; r++){
                int e = tid + r*128;
                int k = e >> 6, n = e & 63;
                brs[r] = Bp[(size_t)(k0 + k)*ldb + n0 + n];
            }
        } else if (BLOAD == 1){
#pragma unroll
            for (int r = 0; r < RB; r++){
                int e = tid + r*128;
                int k = e / (BN/2);
                int n = (e % (BN/2)) * 2;
                brv[r] = *(const float2*)&Bp[(size_t)(k0 + k)*ldb + n0 + n];
            }
        } else {
#pragma unroll
            for (int r = 0; r < RB; r++){
                int e = tid + r*128;
                int n = e >> 2, k = (e & 3)*2;
                brv[r] = *(const float2*)&Bp[(size_t)(n0 + n)*ldb + k0 + k];
            }
        }
    };
    auto stTile = [&](int buf){
        As[buf][0][tid]=ar0.x; As[buf][1][tid]=ar0.y;
        As[buf][2][tid]=ar0.z; As[buf][3][tid]=ar0.w;
        As[buf][4][tid]=ar1.x; As[buf][5][tid]=ar1.y;
        As[buf][6][tid]=ar1.z; As[buf][7][tid]=ar1.w;
        if (BLOAD == 0){
#pragma unroll
            for (int r = 0; r < RB; r++){
                int e = tid + r*128;
                int k = e >> 6, n = e & 63;
                *(float2*)&Bs[buf][k][2*n] = make_float2(brs[r], brs[r]);
            }
        } else if (BLOAD == 1){
#pragma unroll
            for (int r = 0; r < RB; r++){
                int e = tid + r*128;
                int k = e / (BN/2);
                int n = (e % (BN/2)) * 2;
                *(float4*)&Bs[buf][k][2*n] = make_float4(brv[r].x, brv[r].x, brv[r].y, brv[r].y);
            }
        } else {
#pragma unroll
            for (int r = 0; r < RB; r++){
                int e = tid + r*128;
                int n = e >> 2, k = (e & 3)*2;
                *(float2*)&Bs[buf][k  ][2*n] = make_float2(brv[r].x, brv[r].x);
                *(float2*)&Bs[buf][k+1][2*n] = make_float2(brv[r].y, brv[r].y);
            }
        }
    };

    ldTile(0); stTile(0);
    __syncthreads();
    const int T = Kc / 8;
    for (int t = 0; t < T; ++t){
        int cur = t & 1;
        if (t + 1 < T) ldTile((t + 1) * 8);
#pragma unroll
        for (int kk = 0; kk < 8; ++kk){
            const float* arow = &As[cur][kk][tm*8];
            longlong2 a01 = *(const longlong2*)(arow);
            longlong2 a23 = *(const longlong2*)(arow + 4);
            ull av[4] = {(ull)a01.x, (ull)a01.y, (ull)a23.x, (ull)a23.y};
            ull bv[TN];
#pragma unroll
            for (int jq = 0; jq < TN/2; jq++){
                longlong2 bq = *(const longlong2*)&Bs[cur][kk][(tn*TN + 2*jq)*2];
                bv[2*jq] = (ull)bq.x; bv[2*jq+1] = (ull)bq.y;
            }
#pragma unroll
            for (int i = 0; i < 4; i++)
#pragma unroll
                for (int j = 0; j < TN; j++) ffma2(acc[i][j], av[i], bv[j]);
        }
        if (t + 1 < T) stTile(cur ^ 1);
        __syncthreads();
    }

#pragma unroll
    for (int i = 0; i < 4; i++){
        int m = m0 + tm*8 + 2*i;
#pragma unroll
        for (int j = 0; j < TN; j++){
            float2 v = unpack2(acc[i][j]);
            int n = n0 + tn*TN + j;
            Cp[(size_t)m*N + n]     = v.x;
            Cp[(size_t)(m+1)*N + n] = v.y;
        }
    }
}

// ------------------------- split-K reduce + bias + activation -------------------------
template<int S>
__global__ __launch_bounds__(256) void reduce_act(
    const float* __restrict__ part, const float* __restrict__ bias,
    float* __restrict__ C, int M, int N, int ldc, size_t sC, int relu)
{
    const int b = blockIdx.y;
    const int idx = blockIdx.x*256 + threadIdx.x;     // float4 index
    const int total = M*N/4;
    if (idx >= total) return;
    const int m = (idx*4) / N, n = (idx*4) % N;
    const float4* p = (const float4*)(part + (size_t)b*S*M*N);
    float4 a = p[idx];
#pragma unroll
    for (int s = 1; s < S; s++){
        float4 v = p[idx + (size_t)s*total];
        a.x += v.x; a.y += v.y; a.z += v.z; a.w += v.w;
    }
    float bv = bias[m];
    a.x += bv; a.y += bv; a.z += bv; a.w += bv;
    if (relu){
        a.x = fmaxf(a.x, 0.f); a.y = fmaxf(a.y, 0.f);
        a.z = fmaxf(a.z, 0.f); a.w = fmaxf(a.w, 0.f);
    }
    *(float4*)&C[(size_t)b*sC + (size_t)m*ldc + n] = a;
}

// ------------------------- feat2 -> g_lf tiled transpose -------------------------
__global__ void transpose_lf(){
    __shared__ float s[32][33];
    int b = blockIdx.z;
    int t0 = blockIdx.x * 32;
    int c0 = blockIdx.y * 32;
    int x = threadIdx.x, y = threadIdx.y;   // 32 x 8
#pragma unroll
    for (int r = 0; r < 32; r += 8)
        s[y + r][x] = g_feat2[((size_t)b*512 + c0 + y + r)*256 + t0 + x];
    __syncthreads();
#pragma unroll
    for (int r = 0; r < 32; r += 8)
        g_lf[((size_t)b*256 + t0 + y + r)*512 + c0 + x] = s[x][y + r];
}

// ------------------------- pad/reorder stage weights -------------------------
__global__ void pad_w(const float* __restrict__ w0, const float* __restrict__ w1){
    int i = blockIdx.x*256 + threadIdx.x;
    if (i >= 2*DH*KPAD) return;
    int s = i / (DH*KPAD);
    int r = i - s*(DH*KPAD);
    int m = r / KPAD, k = r - m*KPAD;
    const float* w = s ? w1 : w0;
    float v = 0.f;
    if (k < 512) v = w[m*515 + 3 + k];          // cond channels
    else if (k < 515) v = w[m*515 + (k - 512)]; // pcd xyz
    g_w1p[i] = v;
}

// ------------------------- camera setup -------------------------
__global__ void setup_w2c_kernel(const float* __restrict__ c2w)
{
    int b = threadIdx.x;
    if (b >= BATCH) return;
    float m[4][4], inv[4][4];
    for (int r = 0; r < 4; r++)
        for (int c = 0; c < 4; c++) {
            float v = c2w[b*16 + r*4 + c];
            if (r < 3 && (c == 1 || c == 2)) v = -v;
            m[r][c] = v;
            inv[r][c] = (r == c) ? 1.f : 0.f;
        }
    for (int col = 0; col < 4; col++) {
        int piv = col; float best = fabsf(m[col][col]);
        for (int r = col+1; r < 4; r++){ float a = fabsf(m[r][col]); if (a > best){ best = a; piv = r; } }
        if (piv != col)
            for (int c = 0; c < 4; c++){
                float t = m[col][c]; m[col][c] = m[piv][c]; m[piv][c] = t;
                t = inv[col][c]; inv[col][c] = inv[piv][c]; inv[piv][c] = t;
            }
        float d = 1.f / m[col][col];
        for (int c = 0; c < 4; c++){ m[col][c] *= d; inv[col][c] *= d; }
        for (int r = 0; r < 4; r++)
            if (r != col){
                float f = m[r][col];
                for (int c = 0; c < 4; c++){ m[r][c] -= f*m[col][c]; inv[r][c] -= f*inv[col][c]; }
            }
    }
    for (int i = 0; i < 12; i++) g_w2c[b*12 + i] = inv[i/4][i%4];
}

// ------------------------- z-buffer visibility -------------------------
__global__ void reset_zbuf(){
    int i = blockIdx.x*256 + threadIdx.x;
    if (i < BATCH*NPIX) g_zbuf[i] = ~0ULL;
}

__global__ void project(const float* __restrict__ pts, const float* __restrict__ Kin, int Npts){
    int i = blockIdx.x*256 + threadIdx.x;
    if (i >= BATCH*Npts) return;
    int b = i / Npts, n = i - b*Npts;
    const float* w = g_w2c + b*12;
    float x = pts[(size_t)i*3], y = pts[(size_t)i*3+1], z = pts[(size_t)i*3+2];
    float camx = w[0]*x + w[1]*y + w[2]*z + w[3];
    float camy = w[4]*x + w[5]*y + w[6]*z + w[7];
    float camz = w[8]*x + w[9]*y + w[10]*z + w[11];
    float zs = (fabsf(camz) > 1e-8f) ? camz : 1e-8f;
    float fx = Kin[b*9+0], cxk = Kin[b*9+2], fy = Kin[b*9+4], cyk = Kin[b*9+5];
    float px = fx*camx/zs + cxk;
    float py = fy*camy/zs + cyk;
    int ix = (int)floorf(px), iy = (int)floorf(py);
    bool valid = (camz > 1e-6f) && ix >= 0 && ix < IMG && iy >= 0 && iy < IMG;
    int pix = valid ? iy*IMG + ix : -1;
    g_pixb[b*N1 + n] = pix;
    g_pzb[b*N1 + n] = camz;
    if (valid)
        atomicMin(&g_zbuf[(size_t)b*NPIX + pix], ((ull)__float_as_uint(camz) << 32) | (unsigned)n);
}

// ------------------------- gather cond + visibility check -------------------------
__global__ __launch_bounds__(128) void gather_cond(const float* __restrict__ pts, int Npts){
    int blk = blockIdx.x;
    int b = blk / Npts, n = blk - b*Npts;
    int tid = threadIdx.x;
    float* xo = g_x + ((size_t)b*N1 + n)*XLD;
    if (tid < 3) xo[512 + tid] = pts[(size_t)blk*3 + tid];
    int pix = g_pixb[b*N1 + n];
    bool vis = false;
    if (pix >= 0){
        ull key = ((ull)__float_as_uint(g_pzb[b*N1 + n]) << 32) | (unsigned)n;
        vis = (g_zbuf[(size_t)b*NPIX + pix] == key);
    }
    if (!vis){
        *(float4*)&xo[tid*4] = make_float4(0.f, 0.f, 0.f, 0.f);
        return;
    }
    int iy = pix / IMG, ix = pix - iy*IMG;
    float sfx = (ix + 0.5f)*(16.f/224.f) - 0.5f;
    float sfy = (iy + 0.5f)*(16.f/224.f) - 0.5f;
    int jx0 = (int)floorf(sfx); float fxw = sfx - (float)jx0;
    int jy0 = (int)floorf(sfy); float fyw = sfy - (float)jy0;
    int x0 = min(max(jx0, 0), 15), x1 = min(max(jx0+1, 0), 15);
    int y0 = min(max(jy0, 0), 15), y1 = min(max(jy0+1, 0), 15);
    float w00 = (1.f-fyw)*(1.f-fxw), w01 = (1.f-fyw)*fxw;
    float w10 = fyw*(1.f-fxw),       w11 = fyw*fxw;
    const float4* l00 = (const float4*)(g_lf + ((size_t)b*256 + y0*16 + x0)*512);
    const float4* l01 = (const float4*)(g_lf + ((size_t)b*256 + y0*16 + x1)*512);
    const float4* l10 = (const float4*)(g_lf + ((size_t)b*256 + y1*16 + x0)*512);
    const float4* l11 = (const float4*)(g_lf + ((size_t)b*256 + y1*16 + x1)*512);
    float4 v00 = l00[tid], v01 = l01[tid], v10 = l10[tid], v11 = l11[tid];
    float4 o;
    o.x = w00*v00.x + w01*v01.x + w10*v10.x + w11*v11.x;
    o.y = w00*v00.y + w01*v01.y + w10*v10.y + w11*v11.y;
    o.z = w00*v00.z + w01*v01.z + w10*v10.z + w11*v11.z;
    o.w = w00*v00.w + w01*v01.w + w10*v10.w + w11*v11.w;
    *(float4*)&xo[tid*4] = o;
}

// ------------------------- output head: tanh offsets + scatter -------------------------
template <int F>
__global__ __launch_bounds__(128) void stage_out(
    const float* __restrict__ ow, const float* __restrict__ ob,
    const float* __restrict__ pts_in, float* __restrict__ pts_out, int Npts)
{
    __shared__ float s_ow[F*3][DH];
    __shared__ float s_ob[F*3];
    const int b = blockIdx.y;
    const int tid = threadIdx.x;
    for (int i = tid; i < F*3*DH; i += 128) s_ow[i / DH][i % DH] = ow[i];
    if (tid < F*3) s_ob[tid] = ob[tid];
    __syncthreads();
    const int n = blockIdx.x*128 + tid;
    if (n >= Npts) return;
    const float* hp = g_h + (size_t)b*DH*HLD;
    float acc[F*3];
#pragma unroll
    for (int r = 0; r < F*3; r++) acc[r] = s_ob[r];
    for (int o = 0; o < DH; o++){
        float hv = hp[(size_t)o*HLD + n];
#pragma unroll
        for (int r = 0; r < F*3; r++) acc[r] += s_ow[r][o] * hv;
    }
    float p[3];
    p[0] = pts_in[(size_t)(b*Npts + n)*3 + 0];
    p[1] = pts_in[(size_t)(b*Npts + n)*3 + 1];
    p[2] = pts_in[(size_t)(b*Npts + n)*3 + 2];
#pragma unroll
    for (int k = 0; k < F; k++)
#pragma unroll
        for (int c = 0; c < 3; c++){
            size_t oidx = ((size_t)b*Npts*F + (size_t)n*F + k)*3 + c;
            pts_out[oidx] = p[c] + tanhf(acc[k*3 + c]);
        }
}

// ------------------------- launch -------------------------
extern "C" void kernel_launch(void* const* d_in, const int* in_sizes, int n_in,
                              void* d_out, int out_size)
{
    const float* points = (const float*)d_in[0];
    const float* tokens = (const float*)d_in[1];
    const float* c2w    = (const float*)d_in[2];
    const float* Kin    = (const float*)d_in[3];
    const float* w1     = (const float*)d_in[4];
    const float* b1     = (const float*)d_in[5];
    const float* w2     = (const float*)d_in[6];
    const float* b2     = (const float*)d_in[7];
    const float* s0w1   = (const float*)d_in[8];
    const float* s0b1   = (const float*)d_in[9];
    const float* s0ow   = (const float*)d_in[10];
    const float* s0ob   = (const float*)d_in[11];
    const float* s1w1   = (const float*)d_in[12];
    const float* s1b1   = (const float*)d_in[13];
    const float* s1ow   = (const float*)d_in[14];
    const float* s1ob   = (const float*)d_in[15];

    float* out0 = (float*)d_out;                       // (4, 2048, 3)
    float* out1 = out0 + (size_t)BATCH*N0*F0*3;        // (4, 16384, 3)

    float *part, *feat1, *feat2, *w1p, *xbuf, *hbuf;
    cudaGetSymbolAddress((void**)&part,  g_part);
    cudaGetSymbolAddress((void**)&feat1, g_feat1);
    cudaGetSymbolAddress((void**)&feat2, g_feat2);
    cudaGetSymbolAddress((void**)&w1p,   g_w1p);
    cudaGetSymbolAddress((void**)&xbuf,  g_x);
    cudaGetSymbolAddress((void**)&hbuf,  g_h);

    pad_w<<<(2*DH*KPAD + 255)/256, 256>>>(s0w1, s1w1);
    setup_w2c_kernel<<<1, BATCH>>>(c2w);
    reset_zbuf<<<(BATCH*NPIX + 255)/256, 256>>>();

    // token MLP (token 0 dropped -> N=256), split-K x4
    gemm_k<64,8,0,SPL><<<dim3(4, 8, BATCH*SPL), 128>>>(w1, tokens + 1, part,
        1152/SPL, 1152, 257, 256, (size_t)1152*257);
    reduce_act<SPL><<<dim3(1024*256/4/256, BATCH), 256>>>(part, b1, feat1,
        1024, 256, 256, (size_t)1024*256, 1);
    gemm_k<32,4,1,SPL><<<dim3(8, 4, BATCH*SPL), 128>>>(w2, feat1, part,
        1024/SPL, 1024, 256, 256, (size_t)1024*256);
    reduce_act<SPL><<<dim3(512*256/4/256, BATCH), 256>>>(part, b2, feat2,
        512, 256, 256, (size_t)512*256, 0);
    transpose_lf<<<dim3(8, 16, BATCH), dim3(32, 8)>>>();

    // stage 0
    project<<<(BATCH*N0 + 255)/256, 256>>>(points, Kin, N0);
    gather_cond<<<BATCH*N0, 128>>>(points, N0);
    gemm_k<32,4,2,SPL><<<dim3(16, 1, BATCH*SPL), 128>>>(w1p, xbuf, part,
        KPAD/SPL, KPAD, XLD, 512, (size_t)N1*XLD);
    reduce_act<SPL><<<dim3(128*512/4/256, BATCH), 256>>>(part, s0b1, hbuf,
        128, 512, HLD, (size_t)DH*HLD, 1);
    stage_out<F0><<<dim3(N0/128, BATCH), 128>>>(s0ow, s0ob, points, out0, N0);

    // stage 1
    reset_zbuf<<<(BATCH*NPIX + 255)/256, 256>>>();
    project<<<(BATCH*N1 + 255)/256, 256>>>(out0, Kin, N1);
    gather_cond<<<BATCH*N1, 128>>>(out0, N1);
    gemm_k<64,8,2,SPL><<<dim3(32, 1, BATCH*SPL), 128>>>(w1p + DH*KPAD, xbuf, part,
        KPAD/SPL, KPAD, XLD, 2048, (size_t)N1*XLD);
    reduce_act<SPL><<<dim3(128*2048/4/256, BATCH), 256>>>(part, s1b1, hbuf,
        128, 2048, HLD, (size_t)DH*HLD, 1);
    stage_out<F1><<<dim3(N1/128, BATCH), 128>>>(s1ow, s1ob, out0, out1, N1);
}

// round 4
// speedup vs baseline: 2.0756x; 1.1777x over previous
#include <cuda_runtime.h>
#include <math.h>

#define BATCH 4
#define IMG 224
#define NPIX (IMG*IMG)
#define N0 512
#define F0 4
#define N1 2048
#define F1 8
#define KPAD 544          // padded 3+512 -> 544 (=4*136, 136=17*8)
#define XLD 544
#define HLD 2048
#define DH 128
#define SPL 4             // split-K factor

typedef unsigned long long ull;

// ------------------------- scratch -------------------------
__device__ float g_part[(size_t)BATCH*SPL*1024*256];   // split-K partials (max config)
__device__ float g_feat1[(size_t)BATCH*1024*256];
__device__ float g_feat2[(size_t)BATCH*512*256];
__device__ float g_lf[(size_t)BATCH*256*512];          // [b][cell][c]
__device__ float g_w2c[BATCH*12];
__device__ float g_w1p[2*DH*KPAD];                     // padded/reordered stage weights
__device__ int   g_pixb[BATCH*N1];
__device__ float g_pzb[BATCH*N1];
__device__ ull   g_zbuf[BATCH*NPIX];
__device__ float g_x[(size_t)BATCH*N1*XLD];            // [b][n][k]: cond 0..511, pcd 512..514, pad zero
__device__ float g_h[(size_t)BATCH*DH*HLD];

// ------------------------- f32x2 helpers -------------------------
__device__ __forceinline__ void ffma2(ull &d, ull a, ull b){
    asm("fma.rn.f32x2 %0, %1, %2, %0;" : "+l"(d) : "l"(a), "l"(b));
}
__device__ __forceinline__ float2 unpack2(ull v){
    float2 r; asm("mov.b64 {%0,%1}, %2;" : "=f"(r.x), "=f"(r.y) : "l"(v)); return r;
}

// ------------------------- packed-fp32 split-K GEMM, 64x64 tile -------------------------
// Microtile per thread: 4 M-rows (2 f32x2 pairs) x 8 N-cols. 128 threads = 16(M) x 8(N).
// BLOAD: 0 = scalar row-major B (odd ldb), 1 = vec2 row-major B, 2 = B transposed (N x ldb).
// blockIdx.z = b*S + s. Raw partials -> Cpart[(b*S+s)][M][N], M = gridDim.y*64.
template<int BLOAD, int S>
__global__ __launch_bounds__(128, 5) void gemm_k(
    const float* __restrict__ A, const float* __restrict__ B,
    float* __restrict__ Cpart, int Kc, int lda, int ldb, int N, size_t sB)
{
    __shared__ __align__(16) float As[2][8][64];
    __shared__ __align__(16) float Bs[2][8][136];
    const int tid = threadIdx.x;
    const int m0 = blockIdx.y * 64;
    const int n0 = blockIdx.x * 64;
    const int M  = gridDim.y * 64;
    const int bz = blockIdx.z;
    const int b  = bz / S, s = bz % S;
    const float* Bp = B + (size_t)b * sB + (BLOAD == 2 ? (size_t)s*Kc : (size_t)s*Kc*ldb);
    float* Cp = Cpart + (size_t)bz * M * N;
    const int tm = tid & 15, tn = tid >> 4;

    ull acc[2][8];
#pragma unroll
    for (int i = 0; i < 2; i++)
#pragma unroll
        for (int j = 0; j < 8; j++) acc[i][j] = 0ULL;

    float4 ar;                 // A prefetch: row m0+tid/2, 4 k's
    float  brs[4];             // BLOAD 0
    float2 brv[2];             // BLOAD 1
    float4 br4;                // BLOAD 2
    const float* Ap = A + (size_t)(m0 + (tid >> 1)) * lda + (size_t)s * Kc + (tid & 1) * 4;

    auto ldTile = [&](int k0){
        ar = *(const float4*)(Ap + k0);
        if (BLOAD == 0){
#pragma unroll
            for (int r = 0; r < 4; r++){
                int e = tid + r*128;
                int k = e >> 6, n = e & 63;
                brs[r] = Bp[(size_t)(k0 + k)*ldb + n0 + n];
            }
        } else if (BLOAD == 1){
#pragma unroll
            for (int r = 0; r < 2; r++){
                int e = tid + r*128;
                int k = e >> 5, n = (e & 31) * 2;
                brv[r] = *(const float2*)&Bp[(size_t)(k0 + k)*ldb + n0 + n];
            }
        } else {
            int n = tid >> 1, k = (tid & 1) * 4;
            br4 = *(const float4*)&Bp[(size_t)(n0 + n)*ldb + k0 + k];
        }
    };
    auto stTile = [&](int buf){
        {
            int m = tid >> 1, k = (tid & 1) * 4;
            As[buf][k+0][m] = ar.x; As[buf][k+1][m] = ar.y;
            As[buf][k+2][m] = ar.z; As[buf][k+3][m] = ar.w;
        }
        if (BLOAD == 0){
#pragma unroll
            for (int r = 0; r < 4; r++){
                int e = tid + r*128;
                int k = e >> 6, n = e & 63;
                *(float2*)&Bs[buf][k][2*n] = make_float2(brs[r], brs[r]);
            }
        } else if (BLOAD == 1){
#pragma unroll
            for (int r = 0; r < 2; r++){
                int e = tid + r*128;
                int k = e >> 5, n = (e & 31) * 2;
                *(float4*)&Bs[buf][k][2*n] = make_float4(brv[r].x, brv[r].x, brv[r].y, brv[r].y);
            }
        } else {
            int n = tid >> 1, k = (tid & 1) * 4;
            *(float2*)&Bs[buf][k+0][2*n] = make_float2(br4.x, br4.x);
            *(float2*)&Bs[buf][k+1][2*n] = make_float2(br4.y, br4.y);
            *(float2*)&Bs[buf][k+2][2*n] = make_float2(br4.z, br4.z);
            *(float2*)&Bs[buf][k+3][2*n] = make_float2(br4.w, br4.w);
        }
    };

    ldTile(0); stTile(0);
    __syncthreads();
    const int T = Kc / 8;
    for (int t = 0; t < T; ++t){
        int cur = t & 1;
        if (t + 1 < T) ldTile((t + 1) * 8);
#pragma unroll
        for (int kk = 0; kk < 8; ++kk){
            longlong2 a01 = *(const longlong2*)&As[cur][kk][tm*4];
            ull av[2] = {(ull)a01.x, (ull)a01.y};
            ull bv[8];
#pragma unroll
            for (int jq = 0; jq < 4; jq++){
                longlong2 bq = *(const longlong2*)&Bs[cur][kk][tn*16 + 4*jq];
                bv[2*jq] = (ull)bq.x; bv[2*jq+1] = (ull)bq.y;
            }
#pragma unroll
            for (int i = 0; i < 2; i++)
#pragma unroll
                for (int j = 0; j < 8; j++) ffma2(acc[i][j], av[i], bv[j]);
        }
        if (t + 1 < T) stTile(cur ^ 1);
        __syncthreads();
    }

#pragma unroll
    for (int i = 0; i < 2; i++){
        int m = m0 + tm*4 + 2*i;
#pragma unroll
        for (int j = 0; j < 8; j++){
            float2 v = unpack2(acc[i][j]);
            int n = n0 + tn*8 + j;
            Cp[(size_t)m*N + n]     = v.x;
            Cp[(size_t)(m+1)*N + n] = v.y;
        }
    }
}

// ------------------------- split-K reduce + bias + activation -------------------------
template<int S>
__global__ __launch_bounds__(256) void reduce_act(
    const float* __restrict__ part, const float* __restrict__ bias,
    float* __restrict__ C, int M, int N, int ldc, size_t sC, int relu)
{
    const int b = blockIdx.y;
    const int idx = blockIdx.x*256 + threadIdx.x;     // float4 index
    const int total = M*N/4;
    if (idx >= total) return;
    const int m = (idx*4) / N, n = (idx*4) % N;
    const float4* p = (const float4*)(part + (size_t)b*S*M*N);
    float4 a = p[idx];
#pragma unroll
    for (int s = 1; s < S; s++){
        float4 v = p[idx + (size_t)s*total];
        a.x += v.x; a.y += v.y; a.z += v.z; a.w += v.w;
    }
    float bv = bias[m];
    a.x += bv; a.y += bv; a.z += bv; a.w += bv;
    if (relu){
        a.x = fmaxf(a.x, 0.f); a.y = fmaxf(a.y, 0.f);
        a.z = fmaxf(a.z, 0.f); a.w = fmaxf(a.w, 0.f);
    }
    *(float4*)&C[(size_t)b*sC + (size_t)m*ldc + n] = a;
}

// ------------------------- feat2 -> g_lf tiled transpose -------------------------
__global__ void transpose_lf(){
    __shared__ float s[32][33];
    int b = blockIdx.z;
    int t0 = blockIdx.x * 32;
    int c0 = blockIdx.y * 32;
    int x = threadIdx.x, y = threadIdx.y;   // 32 x 8
#pragma unroll
    for (int r = 0; r < 32; r += 8)
        s[y + r][x] = g_feat2[((size_t)b*512 + c0 + y + r)*256 + t0 + x];
    __syncthreads();
#pragma unroll
    for (int r = 0; r < 32; r += 8)
        g_lf[((size_t)b*256 + t0 + y + r)*512 + c0 + x] = s[x][y + r];
}

// ------------------------- pad/reorder stage weights -------------------------
__global__ void pad_w(const float* __restrict__ w0, const float* __restrict__ w1){
    int i = blockIdx.x*256 + threadIdx.x;
    if (i >= 2*DH*KPAD) return;
    int s = i / (DH*KPAD);
    int r = i - s*(DH*KPAD);
    int m = r / KPAD, k = r - m*KPAD;
    const float* w = s ? w1 : w0;
    float v = 0.f;
    if (k < 512) v = w[m*515 + 3 + k];          // cond channels
    else if (k < 515) v = w[m*515 + (k - 512)]; // pcd xyz
    g_w1p[i] = v;
}

// ------------------------- camera setup -------------------------
__global__ void setup_w2c_kernel(const float* __restrict__ c2w)
{
    int b = threadIdx.x;
    if (b >= BATCH) return;
    float m[4][4], inv[4][4];
    for (int r = 0; r < 4; r++)
        for (int c = 0; c < 4; c++) {
            float v = c2w[b*16 + r*4 + c];
            if (r < 3 && (c == 1 || c == 2)) v = -v;
            m[r][c] = v;
            inv[r][c] = (r == c) ? 1.f : 0.f;
        }
    for (int col = 0; col < 4; col++) {
        int piv = col; float best = fabsf(m[col][col]);
        for (int r = col+1; r < 4; r++){ float a = fabsf(m[r][col]); if (a > best){ best = a; piv = r; } }
        if (piv != col)
            for (int c = 0; c < 4; c++){
                float t = m[col][c]; m[col][c] = m[piv][c]; m[piv][c] = t;
                t = inv[col][c]; inv[col][c] = inv[piv][c]; inv[piv][c] = t;
            }
        float d = 1.f / m[col][col];
        for (int c = 0; c < 4; c++){ m[col][c] *= d; inv[col][c] *= d; }
        for (int r = 0; r < 4; r++)
            if (r != col){
                float f = m[r][col];
                for (int c = 0; c < 4; c++){ m[r][c] -= f*m[col][c]; inv[r][c] -= f*inv[col][c]; }
            }
    }
    for (int i = 0; i < 12; i++) g_w2c[b*12 + i] = inv[i/4][i%4];
}

// ------------------------- z-buffer visibility -------------------------
__global__ void reset_zbuf(){
    int i = blockIdx.x*256 + threadIdx.x;
    if (i < BATCH*NPIX) g_zbuf[i] = ~0ULL;
}

__global__ void project(const float* __restrict__ pts, const float* __restrict__ Kin, int Npts){
    int i = blockIdx.x*256 + threadIdx.x;
    if (i >= BATCH*Npts) return;
    int b = i / Npts, n = i - b*Npts;
    const float* w = g_w2c + b*12;
    float x = pts[(size_t)i*3], y = pts[(size_t)i*3+1], z = pts[(size_t)i*3+2];
    float camx = w[0]*x + w[1]*y + w[2]*z + w[3];
    float camy = w[4]*x + w[5]*y + w[6]*z + w[7];
    float camz = w[8]*x + w[9]*y + w[10]*z + w[11];
    float zs = (fabsf(camz) > 1e-8f) ? camz : 1e-8f;
    float fx = Kin[b*9+0], cxk = Kin[b*9+2], fy = Kin[b*9+4], cyk = Kin[b*9+5];
    float px = fx*camx/zs + cxk;
    float py = fy*camy/zs + cyk;
    int ix = (int)floorf(px), iy = (int)floorf(py);
    bool valid = (camz > 1e-6f) && ix >= 0 && ix < IMG && iy >= 0 && iy < IMG;
    int pix = valid ? iy*IMG + ix : -1;
    g_pixb[b*N1 + n] = pix;
    g_pzb[b*N1 + n] = camz;
    if (valid)
        atomicMin(&g_zbuf[(size_t)b*NPIX + pix], ((ull)__float_as_uint(camz) << 32) | (unsigned)n);
}

// ------------------------- gather cond + visibility check -------------------------
__global__ __launch_bounds__(128) void gather_cond(const float* __restrict__ pts, int Npts){
    int blk = blockIdx.x;
    int b = blk / Npts, n = blk - b*Npts;
    int tid = threadIdx.x;
    float* xo = g_x + ((size_t)b*N1 + n)*XLD;
    if (tid < 3) xo[512 + tid] = pts[(size_t)blk*3 + tid];
    int pix = g_pixb[b*N1 + n];
    bool vis = false;
    if (pix >= 0){
        ull key = ((ull)__float_as_uint(g_pzb[b*N1 + n]) << 32) | (unsigned)n;
        vis = (g_zbuf[(size_t)b*NPIX + pix] == key);
    }
    if (!vis){
        *(float4*)&xo[tid*4] = make_float4(0.f, 0.f, 0.f, 0.f);
        return;
    }
    int iy = pix / IMG, ix = pix - iy*IMG;
    float sfx = (ix + 0.5f)*(16.f/224.f) - 0.5f;
    float sfy = (iy + 0.5f)*(16.f/224.f) - 0.5f;
    int jx0 = (int)floorf(sfx); float fxw = sfx - (float)jx0;
    int jy0 = (int)floorf(sfy); float fyw = sfy - (float)jy0;
    int x0 = min(max(jx0, 0), 15), x1 = min(max(jx0+1, 0), 15);
    int y0 = min(max(jy0, 0), 15), y1 = min(max(jy0+1, 0), 15);
    float w00 = (1.f-fyw)*(1.f-fxw), w01 = (1.f-fyw)*fxw;
    float w10 = fyw*(1.f-fxw),       w11 = fyw*fxw;
    const float4* l00 = (const float4*)(g_lf + ((size_t)b*256 + y0*16 + x0)*512);
    const float4* l01 = (const float4*)(g_lf + ((size_t)b*256 + y0*16 + x1)*512);
    const float4* l10 = (const float4*)(g_lf + ((size_t)b*256 + y1*16 + x0)*512);
    const float4* l11 = (const float4*)(g_lf + ((size_t)b*256 + y1*16 + x1)*512);
    float4 v00 = l00[tid], v01 = l01[tid], v10 = l10[tid], v11 = l11[tid];
    float4 o;
    o.x = w00*v00.x + w01*v01.x + w10*v10.x + w11*v11.x;
    o.y = w00*v00.y + w01*v01.y + w10*v10.y + w11*v11.y;
    o.z = w00*v00.z + w01*v01.z + w10*v10.z + w11*v11.z;
    o.w = w00*v00.w + w01*v01.w + w10*v10.w + w11*v11.w;
    *(float4*)&xo[tid*4] = o;
}

// ------------------------- output head: tanh offsets + scatter -------------------------
template <int F>
__global__ __launch_bounds__(128) void stage_out(
    const float* __restrict__ ow, const float* __restrict__ ob,
    const float* __restrict__ pts_in, float* __restrict__ pts_out, int Npts)
{
    __shared__ float s_ow[F*3][DH];
    __shared__ float s_ob[F*3];
    const int b = blockIdx.y;
    const int tid = threadIdx.x;
    for (int i = tid; i < F*3*DH; i += 128) s_ow[i / DH][i % DH] = ow[i];
    if (tid < F*3) s_ob[tid] = ob[tid];
    __syncthreads();
    const int n = blockIdx.x*128 + tid;
    if (n >= Npts) return;
    const float* hp = g_h + (size_t)b*DH*HLD;
    float acc[F*3];
#pragma unroll
    for (int r = 0; r < F*3; r++) acc[r] = s_ob[r];
    for (int o = 0; o < DH; o++){
        float hv = hp[(size_t)o*HLD + n];
#pragma unroll
        for (int r = 0; r < F*3; r++) acc[r] += s_ow[r][o] * hv;
    }
    float p[3];
    p[0] = pts_in[(size_t)(b*Npts + n)*3 + 0];
    p[1] = pts_in[(size_t)(b*Npts + n)*3 + 1];
    p[2] = pts_in[(size_t)(b*Npts + n)*3 + 2];
#pragma unroll
    for (int k = 0; k < F; k++)
#pragma unroll
        for (int c = 0; c < 3; c++){
            size_t oidx = ((size_t)b*Npts*F + (size_t)n*F + k)*3 + c;
            pts_out[oidx] = p[c] + tanhf(acc[k*3 + c]);
        }
}

// ------------------------- launch -------------------------
extern "C" void kernel_launch(void* const* d_in, const int* in_sizes, int n_in,
                              void* d_out, int out_size)
{
    const float* points = (const float*)d_in[0];
    const float* tokens = (const float*)d_in[1];
    const float* c2w    = (const float*)d_in[2];
    const float* Kin    = (const float*)d_in[3];
    const float* w1     = (const float*)d_in[4];
    const float* b1     = (const float*)d_in[5];
    const float* w2     = (const float*)d_in[6];
    const float* b2     = (const float*)d_in[7];
    const float* s0w1   = (const float*)d_in[8];
    const float* s0b1   = (const float*)d_in[9];
    const float* s0ow   = (const float*)d_in[10];
    const float* s0ob   = (const float*)d_in[11];
    const float* s1w1   = (const float*)d_in[12];
    const float* s1b1   = (const float*)d_in[13];
    const float* s1ow   = (const float*)d_in[14];
    const float* s1ob   = (const float*)d_in[15];

    float* out0 = (float*)d_out;                       // (4, 2048, 3)
    float* out1 = out0 + (size_t)BATCH*N0*F0*3;        // (4, 16384, 3)

    float *part, *feat1, *feat2, *w1p, *xbuf, *hbuf;
    cudaGetSymbolAddress((void**)&part,  g_part);
    cudaGetSymbolAddress((void**)&feat1, g_feat1);
    cudaGetSymbolAddress((void**)&feat2, g_feat2);
    cudaGetSymbolAddress((void**)&w1p,   g_w1p);
    cudaGetSymbolAddress((void**)&xbuf,  g_x);
    cudaGetSymbolAddress((void**)&hbuf,  g_h);

    pad_w<<<(2*DH*KPAD + 255)/256, 256>>>(s0w1, s1w1);
    setup_w2c_kernel<<<1, BATCH>>>(c2w);
    reset_zbuf<<<(BATCH*NPIX + 255)/256, 256>>>();

    // token MLP (token 0 dropped -> N=256), split-K x4
    gemm_k<0,SPL><<<dim3(4, 16, BATCH*SPL), 128>>>(w1, tokens + 1, part,
        1152/SPL, 1152, 257, 256, (size_t)1152*257);
    reduce_act<SPL><<<dim3(1024*256/4/256, BATCH), 256>>>(part, b1, feat1,
        1024, 256, 256, (size_t)1024*256, 1);
    gemm_k<1,SPL><<<dim3(4, 8, BATCH*SPL), 128>>>(w2, feat1, part,
        1024/SPL, 1024, 256, 256, (size_t)1024*256);
    reduce_act<SPL><<<dim3(512*256/4/256, BATCH), 256>>>(part, b2, feat2,
        512, 256, 256, (size_t)512*256, 0);
    transpose_lf<<<dim3(8, 16, BATCH), dim3(32, 8)>>>();

    // stage 0
    project<<<(BATCH*N0 + 255)/256, 256>>>(points, Kin, N0);
    gather_cond<<<BATCH*N0, 128>>>(points, N0);
    gemm_k<2,SPL><<<dim3(8, 2, BATCH*SPL), 128>>>(w1p, xbuf, part,
        KPAD/SPL, KPAD, XLD, 512, (size_t)N1*XLD);
    reduce_act<SPL><<<dim3(128*512/4/256, BATCH), 256>>>(part, s0b1, hbuf,
        128, 512, HLD, (size_t)DH*HLD, 1);
    stage_out<F0><<<dim3(N0/128, BATCH), 128>>>(s0ow, s0ob, points, out0, N0);

    // stage 1
    reset_zbuf<<<(BATCH*NPIX + 255)/256, 256>>>();
    project<<<(BATCH*N1 + 255)/256, 256>>>(out0, Kin, N1);
    gather_cond<<<BATCH*N1, 128>>>(out0, N1);
    gemm_k<2,SPL><<<dim3(32, 2, BATCH*SPL), 128>>>(w1p + DH*KPAD, xbuf, part,
        KPAD/SPL, KPAD, XLD, 2048, (size_t)N1*XLD);
    reduce_act<SPL><<<dim3(128*2048/4/256, BATCH), 256>>>(part, s1b1, hbuf,
        128, 2048, HLD, (size_t)DH*HLD, 1);
    stage_out<F1><<<dim3(N1/128, BATCH), 128>>>(s1ow, s1ob, out0, out1, N1);
}

// round 5
// speedup vs baseline: 2.3893x; 1.1511x over previous
#include <cuda_runtime.h>
#include <math.h>

#define BATCH 4
#define IMG 224
#define NPIX (IMG*IMG)
#define N0 512
#define F0 4
#define N1 2048
#define F1 8
#define KPAD 544          // padded 3+512 -> 544 (=4*136, 136=17*8)
#define XLD 544
#define HLD 2048
#define DH 128
#define SPL 4             // split-K factor

typedef unsigned long long ull;

// ------------------------- scratch -------------------------
__device__ float g_part[(size_t)BATCH*SPL*1024*256];   // split-K partials (max config)
__device__ float g_feat1[(size_t)BATCH*1024*256];
__device__ float g_feat2[(size_t)BATCH*512*256];
__device__ float g_lf[(size_t)BATCH*256*512];          // [b][cell][c]
__device__ float g_w2c[BATCH*12];
__device__ float g_w1p[2*DH*KPAD];                     // padded/reordered stage weights
__device__ int   g_pixb[BATCH*N1];
__device__ float g_pzb[BATCH*N1];
__device__ ull   g_zbuf[BATCH*NPIX];
__device__ float g_x[(size_t)BATCH*N1*XLD];            // [b][n][k]: cond 0..511, pcd 512..514, pad zero
__device__ float g_h[(size_t)BATCH*DH*HLD];

// ------------------------- f32x2 helpers -------------------------
__device__ __forceinline__ void ffma2(ull &d, ull a, ull b){
    asm("fma.rn.f32x2 %0, %1, %2, %0;" : "+l"(d) : "l"(a), "l"(b));
}
__device__ __forceinline__ float2 unpack2(ull v){
    float2 r; asm("mov.b64 {%0,%1}, %2;" : "=f"(r.x), "=f"(r.y) : "l"(v)); return r;
}

// ------------------------- k-pair packed-fp32 split-K GEMM, 64x64 tile -------------------------
// f32x2 lanes = consecutive k (even/odd partial sums). No operand duplication.
// Smem: As[kp][m*2+l] = A[m][2kp+l], Bs[kp][n*2+l] = B[2kp+l][n].
// Thread (tm=tid>>4, tn=tid&15): m = tm*8+i (i 0..7), n = 2*tn + 32*q + r (q 0..1, r 0..1).
// BLOAD: 0 = B row-major [k][n] (any ldb), 2 = B row-major [n][k] (any ldb).
// blockIdx: x = n-tile, y = m-tile, z = b*S + s. Raw partials -> Cpart[(b*S+s)][M][N].
template<int BLOAD, int S>
__global__ __launch_bounds__(128, 4) void gemm_k(
    const float* __restrict__ A, const float* __restrict__ B,
    float* __restrict__ Cpart, int Kc, int lda, int ldb, int N, size_t sB)
{
    __shared__ __align__(16) float As[2][4][128];
    __shared__ __align__(16) float Bs[2][4][256];
    const int tid = threadIdx.x;
    const int m0 = blockIdx.y * 64;
    const int n0 = blockIdx.x * 64;
    const int M  = gridDim.y * 64;
    const int bz = blockIdx.z;
    const int b  = bz / S, s = bz % S;
    const float* Bp = B + (size_t)b * sB + (BLOAD == 2 ? (size_t)s*Kc : (size_t)s*Kc*ldb);
    float* Cp = Cpart + (size_t)bz * ((size_t)M * N);
    const int tm = tid >> 4, tn = tid & 15;

    // loader mapping: lm = row (A) / row n (BLOAD2) / column n (BLOAD0); lh = k-half (0/1)
    const int lm = tid & 63;
    const int lh = tid >> 6;

    const float* ApG = A + (size_t)(m0 + lm) * lda + (size_t)s * Kc + lh*4;
    const float* BpG = (BLOAD == 0)
        ? Bp + (size_t)(lh*4)*ldb + n0 + lm
        : Bp + (size_t)(n0 + lm) * ldb + lh*4;

    ull acc[8][4];
#pragma unroll
    for (int i = 0; i < 8; i++)
#pragma unroll
        for (int j = 0; j < 4; j++) acc[i][j] = 0ULL;

    float4 apre;
    float  bp0, bp1, bp2, bp3;
    float4 bpre;

    auto ldTile = [&](int k0){
        apre = *(const float4*)(ApG + k0);
        if (BLOAD == 0){
            bp0 = BpG[(size_t)(k0    )*ldb];
            bp1 = BpG[(size_t)(k0 + 1)*ldb];
            bp2 = BpG[(size_t)(k0 + 2)*ldb];
            bp3 = BpG[(size_t)(k0 + 3)*ldb];
        } else {
            bpre = *(const float4*)(BpG + k0);
        }
    };
    auto stTile = [&](int buf){
        *(float2*)&As[buf][lh*2  ][lm*2] = make_float2(apre.x, apre.y);
        *(float2*)&As[buf][lh*2+1][lm*2] = make_float2(apre.z, apre.w);
        if (BLOAD == 0){
            *(float2*)&Bs[buf][lh*2  ][lm*2] = make_float2(bp0, bp1);
            *(float2*)&Bs[buf][lh*2+1][lm*2] = make_float2(bp2, bp3);
        } else {
            *(float2*)&Bs[buf][lh*2  ][lm*2] = make_float2(bpre.x, bpre.y);
            *(float2*)&Bs[buf][lh*2+1][lm*2] = make_float2(bpre.z, bpre.w);
        }
    };

    ldTile(0); stTile(0);
    __syncthreads();
    const int T = Kc / 8;
    for (int t = 0; t < T; ++t){
        int cur = t & 1;
        if (t + 1 < T) ldTile((t + 1) * 8);
#pragma unroll
        for (int kp = 0; kp < 4; ++kp){
            ull av[8];
#pragma unroll
            for (int i = 0; i < 4; i++){
                longlong2 aa = *(const longlong2*)&As[cur][kp][16*tm + 4*i];
                av[2*i] = (ull)aa.x; av[2*i+1] = (ull)aa.y;
            }
            ull bv[4];
#pragma unroll
            for (int q = 0; q < 2; q++){
                longlong2 bb = *(const longlong2*)&Bs[cur][kp][4*tn + 64*q];
                bv[2*q] = (ull)bb.x; bv[2*q+1] = (ull)bb.y;
            }
#pragma unroll
            for (int i = 0; i < 8; i++)
#pragma unroll
                for (int j = 0; j < 4; j++) ffma2(acc[i][j], av[i], bv[j]);
        }
        if (t + 1 < T) stTile(cur ^ 1);
        __syncthreads();
    }

#pragma unroll
    for (int i = 0; i < 8; i++){
        int m = m0 + tm*8 + i;
#pragma unroll
        for (int q = 0; q < 2; q++){
            float2 v0 = unpack2(acc[i][2*q]);
            float2 v1 = unpack2(acc[i][2*q+1]);
            int n = n0 + 2*tn + 32*q;
            *(float2*)&Cp[(size_t)m*N + n] = make_float2(v0.x + v0.y, v1.x + v1.y);
        }
    }
}

// ------------------------- split-K reduce + bias + activation -------------------------
template<int S>
__global__ __launch_bounds__(256) void reduce_act(
    const float* __restrict__ part, const float* __restrict__ bias,
    float* __restrict__ C, int M, int N, int ldc, size_t sC, int relu)
{
    const int b = blockIdx.y;
    const int idx = blockIdx.x*256 + threadIdx.x;     // float4 index
    const int total = M*N/4;
    if (idx >= total) return;
    const int m = (idx*4) / N, n = (idx*4) % N;
    const float4* p = (const float4*)(part + (size_t)b*S*M*N);
    float4 a = p[idx];
#pragma unroll
    for (int s = 1; s < S; s++){
        float4 v = p[idx + (size_t)s*total];
        a.x += v.x; a.y += v.y; a.z += v.z; a.w += v.w;
    }
    float bv = bias[m];
    a.x += bv; a.y += bv; a.z += bv; a.w += bv;
    if (relu){
        a.x = fmaxf(a.x, 0.f); a.y = fmaxf(a.y, 0.f);
        a.z = fmaxf(a.z, 0.f); a.w = fmaxf(a.w, 0.f);
    }
    *(float4*)&C[(size_t)b*sC + (size_t)m*ldc + n] = a;
}

// ------------------------- feat2 -> g_lf tiled transpose -------------------------
__global__ void transpose_lf(){
    __shared__ float s[32][33];
    int b = blockIdx.z;
    int t0 = blockIdx.x * 32;
    int c0 = blockIdx.y * 32;
    int x = threadIdx.x, y = threadIdx.y;   // 32 x 8
#pragma unroll
    for (int r = 0; r < 32; r += 8)
        s[y + r][x] = g_feat2[((size_t)b*512 + c0 + y + r)*256 + t0 + x];
    __syncthreads();
#pragma unroll
    for (int r = 0; r < 32; r += 8)
        g_lf[((size_t)b*256 + t0 + y + r)*512 + c0 + x] = s[x][y + r];
}

// ------------------------- pad/reorder stage weights -------------------------
__global__ void pad_w(const float* __restrict__ w0, const float* __restrict__ w1){
    int i = blockIdx.x*256 + threadIdx.x;
    if (i >= 2*DH*KPAD) return;
    int s = i / (DH*KPAD);
    int r = i - s*(DH*KPAD);
    int m = r / KPAD, k = r - m*KPAD;
    const float* w = s ? w1 : w0;
    float v = 0.f;
    if (k < 512) v = w[m*515 + 3 + k];          // cond channels
    else if (k < 515) v = w[m*515 + (k - 512)]; // pcd xyz
    g_w1p[i] = v;
}

// ------------------------- camera setup -------------------------
__global__ void setup_w2c_kernel(const float* __restrict__ c2w)
{
    int b = threadIdx.x;
    if (b >= BATCH) return;
    float m[4][4], inv[4][4];
    for (int r = 0; r < 4; r++)
        for (int c = 0; c < 4; c++) {
            float v = c2w[b*16 + r*4 + c];
            if (r < 3 && (c == 1 || c == 2)) v = -v;
            m[r][c] = v;
            inv[r][c] = (r == c) ? 1.f : 0.f;
        }
    for (int col = 0; col < 4; col++) {
        int piv = col; float best = fabsf(m[col][col]);
        for (int r = col+1; r < 4; r++){ float a = fabsf(m[r][col]); if (a > best){ best = a; piv = r; } }
        if (piv != col)
            for (int c = 0; c < 4; c++){
                float t = m[col][c]; m[col][c] = m[piv][c]; m[piv][c] = t;
                t = inv[col][c]; inv[col][c] = inv[piv][c]; inv[piv][c] = t;
            }
        float d = 1.f / m[col][col];
        for (int c = 0; c < 4; c++){ m[col][c] *= d; inv[col][c] *= d; }
        for (int r = 0; r < 4; r++)
            if (r != col){
                float f = m[r][col];
                for (int c = 0; c < 4; c++){ m[r][c] -= f*m[col][c]; inv[r][c] -= f*inv[col][c]; }
            }
    }
    for (int i = 0; i < 12; i++) g_w2c[b*12 + i] = inv[i/4][i%4];
}

// ------------------------- z-buffer visibility -------------------------
__global__ void reset_zbuf(){
    int i = blockIdx.x*256 + threadIdx.x;
    if (i < BATCH*NPIX) g_zbuf[i] = ~0ULL;
}

__global__ void project(const float* __restrict__ pts, const float* __restrict__ Kin, int Npts){
    int i = blockIdx.x*256 + threadIdx.x;
    if (i >= BATCH*Npts) return;
    int b = i / Npts, n = i - b*Npts;
    const float* w = g_w2c + b*12;
    float x = pts[(size_t)i*3], y = pts[(size_t)i*3+1], z = pts[(size_t)i*3+2];
    float camx = w[0]*x + w[1]*y + w[2]*z + w[3];
    float camy = w[4]*x + w[5]*y + w[6]*z + w[7];
    float camz = w[8]*x + w[9]*y + w[10]*z + w[11];
    float zs = (fabsf(camz) > 1e-8f) ? camz : 1e-8f;
    float fx = Kin[b*9+0], cxk = Kin[b*9+2], fy = Kin[b*9+4], cyk = Kin[b*9+5];
    float px = fx*camx/zs + cxk;
    float py = fy*camy/zs + cyk;
    int ix = (int)floorf(px), iy = (int)floorf(py);
    bool valid = (camz > 1e-6f) && ix >= 0 && ix < IMG && iy >= 0 && iy < IMG;
    int pix = valid ? iy*IMG + ix : -1;
    g_pixb[b*N1 + n] = pix;
    g_pzb[b*N1 + n] = camz;
    if (valid)
        atomicMin(&g_zbuf[(size_t)b*NPIX + pix], ((ull)__float_as_uint(camz) << 32) | (unsigned)n);
}

// ------------------------- gather cond + visibility check -------------------------
__global__ __launch_bounds__(128) void gather_cond(const float* __restrict__ pts, int Npts){
    int blk = blockIdx.x;
    int b = blk / Npts, n = blk - b*Npts;
    int tid = threadIdx.x;
    float* xo = g_x + ((size_t)b*N1 + n)*XLD;
    if (tid < 3) xo[512 + tid] = pts[(size_t)blk*3 + tid];
    int pix = g_pixb[b*N1 + n];
    bool vis = false;
    if (pix >= 0){
        ull key = ((ull)__float_as_uint(g_pzb[b*N1 + n]) << 32) | (unsigned)n;
        vis = (g_zbuf[(size_t)b*NPIX + pix] == key);
    }
    if (!vis){
        *(float4*)&xo[tid*4] = make_float4(0.f, 0.f, 0.f, 0.f);
        return;
    }
    int iy = pix / IMG, ix = pix - iy*IMG;
    float sfx = (ix + 0.5f)*(16.f/224.f) - 0.5f;
    float sfy = (iy + 0.5f)*(16.f/224.f) - 0.5f;
    int jx0 = (int)floorf(sfx); float fxw = sfx - (float)jx0;
    int jy0 = (int)floorf(sfy); float fyw = sfy - (float)jy0;
    int x0 = min(max(jx0, 0), 15), x1 = min(max(jx0+1, 0), 15);
    int y0 = min(max(jy0, 0), 15), y1 = min(max(jy0+1, 0), 15);
    float w00 = (1.f-fyw)*(1.f-fxw), w01 = (1.f-fyw)*fxw;
    float w10 = fyw*(1.f-fxw),       w11 = fyw*fxw;
    const float4* l00 = (const float4*)(g_lf + ((size_t)b*256 + y0*16 + x0)*512);
    const float4* l01 = (const float4*)(g_lf + ((size_t)b*256 + y0*16 + x1)*512);
    const float4* l10 = (const float4*)(g_lf + ((size_t)b*256 + y1*16 + x0)*512);
    const float4* l11 = (const float4*)(g_lf + ((size_t)b*256 + y1*16 + x1)*512);
    float4 v00 = l00[tid], v01 = l01[tid], v10 = l10[tid], v11 = l11[tid];
    float4 o;
    o.x = w00*v00.x + w01*v01.x + w10*v10.x + w11*v11.x;
    o.y = w00*v00.y + w01*v01.y + w10*v10.y + w11*v11.y;
    o.z = w00*v00.z + w01*v01.z + w10*v10.z + w11*v11.z;
    o.w = w00*v00.w + w01*v01.w + w10*v10.w + w11*v11.w;
    *(float4*)&xo[tid*4] = o;
}

// ------------------------- output head: tanh offsets + scatter -------------------------
template <int F>
__global__ __launch_bounds__(128) void stage_out(
    const float* __restrict__ ow, const float* __restrict__ ob,
    const float* __restrict__ pts_in, float* __restrict__ pts_out, int Npts)
{
    __shared__ float s_ow[F*3][DH];
    __shared__ float s_ob[F*3];
    const int b = blockIdx.y;
    const int tid = threadIdx.x;
    for (int i = tid; i < F*3*DH; i += 128) s_ow[i / DH][i % DH] = ow[i];
    if (tid < F*3) s_ob[tid] = ob[tid];
    __syncthreads();
    const int n = blockIdx.x*128 + tid;
    if (n >= Npts) return;
    const float* hp = g_h + (size_t)b*DH*HLD;
    float acc[F*3];
#pragma unroll
    for (int r = 0; r < F*3; r++) acc[r] = s_ob[r];
    for (int o = 0; o < DH; o++){
        float hv = hp[(size_t)o*HLD + n];
#pragma unroll
        for (int r = 0; r < F*3; r++) acc[r] += s_ow[r][o] * hv;
    }
    float p[3];
    p[0] = pts_in[(size_t)(b*Npts + n)*3 + 0];
    p[1] = pts_in[(size_t)(b*Npts + n)*3 + 1];
    p[2] = pts_in[(size_t)(b*Npts + n)*3 + 2];
#pragma unroll
    for (int k = 0; k < F; k++)
#pragma unroll
        for (int c = 0; c < 3; c++){
            size_t oidx = ((size_t)b*Npts*F + (size_t)n*F + k)*3 + c;
            pts_out[oidx] = p[c] + tanhf(acc[k*3 + c]);
        }
}

// ------------------------- launch -------------------------
extern "C" void kernel_launch(void* const* d_in, const int* in_sizes, int n_in,
                              void* d_out, int out_size)
{
    const float* points = (const float*)d_in[0];
    const float* tokens = (const float*)d_in[1];
    const float* c2w    = (const float*)d_in[2];
    const float* Kin    = (const float*)d_in[3];
    const float* w1     = (const float*)d_in[4];
    const float* b1     = (const float*)d_in[5];
    const float* w2     = (const float*)d_in[6];
    const float* b2     = (const float*)d_in[7];
    const float* s0w1   = (const float*)d_in[8];
    const float* s0b1   = (const float*)d_in[9];
    const float* s0ow   = (const float*)d_in[10];
    const float* s0ob   = (const float*)d_in[11];
    const float* s1w1   = (const float*)d_in[12];
    const float* s1b1   = (const float*)d_in[13];
    const float* s1ow   = (const float*)d_in[14];
    const float* s1ob   = (const float*)d_in[15];

    float* out0 = (float*)d_out;                       // (4, 2048, 3)
    float* out1 = out0 + (size_t)BATCH*N0*F0*3;        // (4, 16384, 3)

    float *part, *feat1, *feat2, *w1p, *xbuf, *hbuf;
    cudaGetSymbolAddress((void**)&part,  g_part);
    cudaGetSymbolAddress((void**)&feat1, g_feat1);
    cudaGetSymbolAddress((void**)&feat2, g_feat2);
    cudaGetSymbolAddress((void**)&w1p,   g_w1p);
    cudaGetSymbolAddress((void**)&xbuf,  g_x);
    cudaGetSymbolAddress((void**)&hbuf,  g_h);

    pad_w<<<(2*DH*KPAD + 255)/256, 256>>>(s0w1, s1w1);
    setup_w2c_kernel<<<1, BATCH>>>(c2w);
    reset_zbuf<<<(BATCH*NPIX + 255)/256, 256>>>();

    // token MLP (token 0 dropped -> N=256), split-K x4
    gemm_k<0,SPL><<<dim3(4, 16, BATCH*SPL), 128>>>(w1, tokens + 1, part,
        1152/SPL, 1152, 257, 256, (size_t)1152*257);
    reduce_act<SPL><<<dim3(1024*256/4/256, BATCH), 256>>>(part, b1, feat1,
        1024, 256, 256, (size_t)1024*256, 1);
    gemm_k<0,SPL><<<dim3(4, 8, BATCH*SPL), 128>>>(w2, feat1, part,
        1024/SPL, 1024, 256, 256, (size_t)1024*256);
    reduce_act<SPL><<<dim3(512*256/4/256, BATCH), 256>>>(part, b2, feat2,
        512, 256, 256, (size_t)512*256, 0);
    transpose_lf<<<dim3(8, 16, BATCH), dim3(32, 8)>>>();

    // stage 0
    project<<<(BATCH*N0 + 255)/256, 256>>>(points, Kin, N0);
    gather_cond<<<BATCH*N0, 128>>>(points, N0);
    gemm_k<2,SPL><<<dim3(8, 2, BATCH*SPL), 128>>>(w1p, xbuf, part,
        KPAD/SPL, KPAD, XLD, 512, (size_t)N1*XLD);
    reduce_act<SPL><<<dim3(128*512/4/256, BATCH), 256>>>(part, s0b1, hbuf,
        128, 512, HLD, (size_t)DH*HLD, 1);
    stage_out<F0><<<dim3(N0/128, BATCH), 128>>>(s0ow, s0ob, points, out0, N0);

    // stage 1
    reset_zbuf<<<(BATCH*NPIX + 255)/256, 256>>>();
    project<<<(BATCH*N1 + 255)/256, 256>>>(out0, Kin, N1);
    gather_cond<<<BATCH*N1, 128>>>(out0, N1);
    gemm_k<2,SPL><<<dim3(32, 2, BATCH*SPL), 128>>>(w1p + DH*KPAD, xbuf, part,
        KPAD/SPL, KPAD, XLD, 2048, (size_t)N1*XLD);
    reduce_act<SPL><<<dim3(128*2048/4/256, BATCH), 256>>>(part, s1b1, hbuf,
        128, 2048, HLD, (size_t)DH*HLD, 1);
    stage_out<F1><<<dim3(N1/128, BATCH), 128>>>(s1ow, s1ob, out0, out1, N1);
}